// round 10
// baseline (speedup 1.0000x reference)
#include <cuda_runtime.h>
#include <cuda_bf16.h>
#include <cstdint>

#define BB 8
#define SS 4096           // WIDTH*WIDTH
#define EE 128
#define WIDTH 64
#define NEDGE 512         // 32 paths * 16 edges per batch
#define MAXD 32           // max unique dsts per src (random 512-into-4096: max ~5)
#define KS 8              // unique srcs handled per matvec block

// Static device scratch
__device__ float g_Wc[EE * EE];       // Wv @ Wp
__device__ float g_bc[EE];            // bv @ Wp
__device__ int   g_usrc[BB][NEDGE];   // unique src node per slot
__device__ int   g_ucnt[BB];          // number of unique srcs
__device__ int   g_cnt[BB][NEDGE];    // unique-dst count per slot
__device__ int   g_dlist[BB][NEDGE][MAXD]; // deduped dst nodes per slot

// ---------------------------------------------------------------------------
// prep: blocks 0..7  -> per-batch dedup + CSR build (deterministic, no atomics)
//       blocks 8..39 -> Wc rows (4 rows per block of 512 thr); block 8 also bc
__global__ __launch_bounds__(512)
void prep_kernel(const int* __restrict__ edges,
                 const float* __restrict__ Wv,
                 const float* __restrict__ Wp,
                 const float* __restrict__ bv) {
    int t = threadIdx.x;
    if (blockIdx.x < BB) {
        int b = blockIdx.x;
        __shared__ int ssrc[NEDGE], sdst[NEDGE];
        __shared__ unsigned char sfs[NEDGE], sfp[NEDGE];
        __shared__ short sslot[NEDGE];

        int4 v = ((const int4*)edges)[(size_t)b * NEDGE + t];
        int s = v.y * WIDTH + v.x;
        int d = v.w * WIDTH + v.z;
        ssrc[t] = s; sdst[t] = d;
        __syncthreads();

        // first-src (fs), first-pair (fp), index of first same-src edge (j0)
        int j0 = t;
        unsigned char fs = 1, fp = 1;
        for (int j = 0; j < t; j++) {
            if (ssrc[j] == s) {
                if (fs) { fs = 0; j0 = j; }
                if (sdst[j] == d) fp = 0;
            }
        }
        sfs[t] = fs; sfp[t] = fp;
        __syncthreads();

        // deterministic slot = prefix count of fs
        if (fs) {
            int slot = 0;
            for (int j = 0; j < t; j++) slot += sfs[j];
            sslot[t] = (short)slot;
        }
        __syncthreads();

        if (fs) {
            int slot = sslot[t];
            g_usrc[b][slot] = s;
            int c = 0;
            for (int j = 0; j < NEDGE; j++)
                if (sfp[j] && ssrc[j] == s) c++;
            g_cnt[b][slot] = c;
        }
        if (t == 0) {
            int c = 0;
            for (int j = 0; j < NEDGE; j++) c += sfs[j];
            g_ucnt[b] = c;
        }
        // deterministic dst-list placement
        if (fp) {
            int idx = 0;
            for (int j = 0; j < t; j++)
                if (sfp[j] && ssrc[j] == s) idx++;
            if (idx < MAXD)
                g_dlist[b][sslot[j0]][idx] = d;
        }
    } else {
        int bi = blockIdx.x - BB;          // 0..31
        int r = bi * 4 + (t >> 7);         // Wc row
        int j = t & 127;                   // Wc col
        const float* wv = Wv + r * EE;
        float a0 = 0.f, a1 = 0.f, a2 = 0.f, a3 = 0.f;
        #pragma unroll
        for (int k = 0; k < EE; k += 4) {
            a0 = fmaf(wv[k],     Wp[(k)     * EE + j], a0);
            a1 = fmaf(wv[k + 1], Wp[(k + 1) * EE + j], a1);
            a2 = fmaf(wv[k + 2], Wp[(k + 2) * EE + j], a2);
            a3 = fmaf(wv[k + 3], Wp[(k + 3) * EE + j], a3);
        }
        g_Wc[r * EE + j] = (a0 + a1) + (a2 + a3);
        if (bi == 0 && t < EE) {
            float bcx = 0.f;
            #pragma unroll 8
            for (int k = 0; k < EE; k++)
                bcx = fmaf(bv[k], Wp[k * EE + t], bcx);
            g_bc[t] = bcx;
        }
    }
}

// ---------------------------------------------------------------------------
// Fill attn region with bp broadcast
__global__ void fill_bp_kernel(float4* __restrict__ out, const float4* __restrict__ bp4) {
    unsigned tid = blockIdx.x * blockDim.x + threadIdx.x;
    out[tid] = bp4[tid & 31];
}

// ---------------------------------------------------------------------------
// matvec: block (g,b) handles KS=8 unique-src slots; Wc read amortized 8x.
// attn[b,src,:] = (sum of deduped values rows) @ Wc + cnt*bc + bp
__global__ __launch_bounds__(128)
void matvec_kernel(float* __restrict__ attn,
                   const float* __restrict__ values,
                   const float* __restrict__ bp) {
    int b = blockIdx.y;
    int g = blockIdx.x;              // 0..63
    int ucnt = g_ucnt[b];
    int base = g * KS;
    if (base >= ucnt) return;
    int e = threadIdx.x;

    __shared__ float accv[KS][EE];
    __shared__ int scnt[KS], ssv[KS];

    if (e < KS) {
        int slot = base + e;
        bool valid = slot < ucnt;
        scnt[e] = valid ? g_cnt[b][slot] : 0;
        ssv[e]  = valid ? g_usrc[b][slot] : 0;
    }
    __syncthreads();

    #pragma unroll
    for (int r = 0; r < KS; r++) {
        float a = 0.f;
        int c = scnt[r];
        for (int i = 0; i < c; i++) {
            int dst = g_dlist[b][base + r][i];
            a += values[((size_t)b * SS + dst) * EE + e];
        }
        accv[r][e] = a;
    }
    __syncthreads();

    float bpe = bp[e], bce = g_bc[e];
    float o[KS];
    #pragma unroll
    for (int r = 0; r < KS; r++) o[r] = fmaf((float)scnt[r], bce, bpe);

    for (int k = 0; k < EE; k++) {
        float w = g_Wc[k * EE + e];
        #pragma unroll
        for (int r = 0; r < KS; r++)
            o[r] = fmaf(accv[r][k], w, o[r]);
    }

    #pragma unroll
    for (int r = 0; r < KS; r++) {
        if (base + r < ucnt)
            attn[((size_t)b * SS + ssv[r]) * EE + e] = o[r];
    }
}

// ---------------------------------------------------------------------------
// Scatter adjacency ones into both A copies (after zeros).
__global__ void set_edges_kernel(float* __restrict__ A1, float* __restrict__ A2,
                                 const int* __restrict__ edges) {
    int b = blockIdx.x;
    int i = threadIdx.x;
    const int4 v = ((const int4*)edges)[(size_t)b * NEDGE + i];
    int src = v.y * WIDTH + v.x;
    int dst = v.w * WIDTH + v.z;
    size_t off = ((size_t)b * SS + src) * SS + dst;
    A1[off] = 1.0f;
    A2[off] = 1.0f;
}

// ---------------------------------------------------------------------------
extern "C" void kernel_launch(void* const* d_in, const int* in_sizes, int n_in,
                              void* d_out, int out_size) {
    (void)in_sizes; (void)n_in; (void)out_size;

    const float* values = (const float*)d_in[2];
    const int*   edges  = (const int*)  d_in[3];
    const float* Wv     = (const float*)d_in[8];
    const float* bv     = (const float*)d_in[9];
    const float* Wp     = (const float*)d_in[10];
    const float* bp     = (const float*)d_in[11];

    float* out  = (float*)d_out;
    float* attn = out;                                    // [B,S,E]
    float* A1   = out + (size_t)BB * SS * EE;             // [B,S,S]
    float* A2   = A1 + (size_t)BB * SS * SS;              // [B,S,S]

    // 1) dedup CSR + combined weights (~3-4 us)
    prep_kernel<<<BB + 32, 512>>>(edges, Wv, Wp, bv);

    // 2) attn := bp broadcast (~5 us)
    {
        unsigned total4 = BB * SS * (EE / 4);             // 1,048,576 float4s
        fill_bp_kernel<<<total4 / 256, 256>>>((float4*)attn, (const float4*)bp);
    }

    // 3) sparse fused matvec over unique srcs (~3-4 us)
    {
        dim3 grid(NEDGE / KS, BB);                        // (64, 8)
        matvec_kernel<<<grid, EE>>>(attn, values, bp);
    }

    // 4) bulk zeros via memset (fastest store path, ~145 us)
    cudaMemsetAsync(A1, 0, 2ull * BB * SS * SS * sizeof(float));

    // 5) adjacency ones (~2 us)
    set_edges_kernel<<<BB, NEDGE>>>(A1, A2, edges);
}

// round 11
// speedup vs baseline: 1.1390x; 1.1390x over previous
#include <cuda_runtime.h>
#include <cuda_bf16.h>
#include <cstdint>

#define BB 8
#define SS 4096           // WIDTH*WIDTH
#define EE 128
#define WIDTH 64
#define NEDGE 512         // 32 paths * 16 edges per batch
#define MAXL 32           // cap on same-src edge list per block

// Combined weights: Wc = Wv @ Wp, bc = bv @ Wp
__device__ float g_Wc[EE * EE];
__device__ float g_bc[EE];

// ---------------------------------------------------------------------------
// combine: Wc[i][j] = sum_k Wv[i][k] * Wp[k][j];  bc[j] = sum_k bv[k]*Wp[k][j]
// grid = EE blocks (row i), block = EE threads (col j)
__global__ void combine_kernel(const float* __restrict__ Wv,
                               const float* __restrict__ Wp,
                               const float* __restrict__ bv) {
    __shared__ float wvrow[EE];
    int i = blockIdx.x, j = threadIdx.x;
    wvrow[j] = Wv[i * EE + j];
    __syncthreads();
    float acc = 0.0f;
    #pragma unroll 16
    for (int k = 0; k < EE; k++)
        acc = fmaf(wvrow[k], Wp[k * EE + j], acc);
    g_Wc[i * EE + j] = acc;
    if (i == 0) {
        float b = 0.0f;
        #pragma unroll 16
        for (int k = 0; k < EE; k++)
            b = fmaf(bv[k], Wp[k * EE + j], b);
        g_bc[j] = b;
    }
}

// ---------------------------------------------------------------------------
// Fill attn region with bp broadcast
__global__ void fill_bp_kernel(float4* __restrict__ out, const float4* __restrict__ bp4) {
    unsigned tid = blockIdx.x * blockDim.x + threadIdx.x;
    out[tid] = bp4[tid & 31];
}

// ---------------------------------------------------------------------------
// Fused output: one block per edge (4096 blocks, 128 thr — proven shape).
// Block i (batch b): if edge i is the FIRST edge with this src, gather all
// same-src dsts (cheap ballot-style collect), dedupe by value (order-free),
// sum raw values rows, one matvec vs Wc, write attn row.
__global__ __launch_bounds__(128)
void fused_out_kernel(float* __restrict__ attn,
                      const float* __restrict__ values,
                      const float* __restrict__ bp,
                      const int* __restrict__ edges) {
    __shared__ int ssrc[NEDGE];
    __shared__ int sdst[NEDGE];
    __shared__ int list[MAXL];
    __shared__ int nlist;
    __shared__ int dupflag;
    __shared__ float accv[EE];

    int b = blockIdx.y;
    int i = blockIdx.x;
    int e = threadIdx.x;

    const int4* eg = (const int4*)(edges + (size_t)b * NEDGE * 4);
    #pragma unroll
    for (int q = 0; q < 4; q++) {
        int t = e + q * EE;
        int4 v = eg[t];
        ssrc[t] = v.y * WIDTH + v.x;
        sdst[t] = v.w * WIDTH + v.z;
    }
    if (e == 0) { nlist = 0; dupflag = 0; }
    __syncthreads();

    int my = ssrc[i];

    // 4 compares/thread: first-src check + same-src dst collection
    #pragma unroll
    for (int q = 0; q < 4; q++) {
        int t = e + q * EE;
        if (ssrc[t] == my) {
            if (t < i) dupflag = 1;               // earlier edge shares src
            int p = atomicAdd(&nlist, 1);         // smem atomic, cheap
            if (p < MAXL) list[p] = sdst[t];
        }
    }
    __syncthreads();
    if (dupflag) return;                          // whole block exits together

    // unique-by-value sum over collected dsts (order-independent => deterministic)
    int n = nlist < MAXL ? nlist : MAXL;
    float acc = 0.0f;
    int m = 0;
    for (int q = 0; q < n; q++) {
        int d = list[q];
        bool uniq = true;
        for (int p = 0; p < q; p++)
            if (list[p] == d) { uniq = false; break; }
        if (uniq) {
            acc += values[((size_t)b * SS + d) * EE + e];
            m++;
        }
    }
    accv[e] = acc;
    __syncthreads();

    // one matvec vs combined weight
    float o = fmaf((float)m, g_bc[e], bp[e]);
    #pragma unroll 16
    for (int k = 0; k < EE; k++)
        o = fmaf(accv[k], g_Wc[k * EE + e], o);

    attn[((size_t)b * SS + my) * EE + e] = o;
}

// ---------------------------------------------------------------------------
// Scatter adjacency ones into both A copies (after zeros).
__global__ void set_edges_kernel(float* __restrict__ A1, float* __restrict__ A2,
                                 const int* __restrict__ edges) {
    int b = blockIdx.x;
    int i = threadIdx.x;
    const int4 v = ((const int4*)edges)[(size_t)b * NEDGE + i];
    int src = v.y * WIDTH + v.x;
    int dst = v.w * WIDTH + v.z;
    size_t off = ((size_t)b * SS + src) * SS + dst;
    A1[off] = 1.0f;
    A2[off] = 1.0f;
}

// ---------------------------------------------------------------------------
extern "C" void kernel_launch(void* const* d_in, const int* in_sizes, int n_in,
                              void* d_out, int out_size) {
    (void)in_sizes; (void)n_in; (void)out_size;

    const float* values = (const float*)d_in[2];
    const int*   edges  = (const int*)  d_in[3];
    const float* Wv     = (const float*)d_in[8];
    const float* bv     = (const float*)d_in[9];
    const float* Wp     = (const float*)d_in[10];
    const float* bp     = (const float*)d_in[11];

    float* out  = (float*)d_out;
    float* attn = out;                                    // [B,S,E]
    float* A1   = out + (size_t)BB * SS * EE;             // [B,S,S]
    float* A2   = A1 + (size_t)BB * SS * SS;              // [B,S,S]

    // 1) bulk zeros via memset (measured fastest store path, ~147 us)
    cudaMemsetAsync(A1, 0, 2ull * BB * SS * SS * sizeof(float));

    // 2) combined weights Wc, bc (~2.5 us)
    combine_kernel<<<EE, EE>>>(Wv, Wp, bv);

    // 3) attn := bp broadcast (~5 us)
    {
        unsigned total4 = BB * SS * (EE / 4);             // 1,048,576 float4s
        fill_bp_kernel<<<total4 / 256, 256>>>((float4*)attn, (const float4*)bp);
    }

    // 4) fused sparse output (~18 us, 4096 blocks)
    {
        dim3 grid(NEDGE, BB);
        fused_out_kernel<<<grid, EE>>>(attn, values, bp, edges);
    }

    // 5) adjacency ones (~2 us)
    set_edges_kernel<<<BB, NEDGE>>>(A1, A2, edges);
}

// round 13
// speedup vs baseline: 1.1771x; 1.0334x over previous
#include <cuda_runtime.h>
#include <cuda_bf16.h>
#include <cstdint>

#define BB 8
#define SS 4096           // WIDTH*WIDTH
#define EE 128
#define WIDTH 64
#define NEDGE 512         // 32 paths * 16 edges per batch
#define MAXL 32           // cap on same-src edge list

// Combined weights: Wc = Wv @ Wp, bc = bv @ Wp
__device__ float g_Wc[EE * EE];
__device__ float g_bc[EE];

// ---------------------------------------------------------------------------
// combine: Wc[i][j] = sum_k Wv[i][k] * Wp[k][j];  bc[j] = sum_k bv[k]*Wp[k][j]
__global__ void combine_kernel(const float* __restrict__ Wv,
                               const float* __restrict__ Wp,
                               const float* __restrict__ bv) {
    __shared__ float wvrow[EE];
    int i = blockIdx.x, j = threadIdx.x;
    wvrow[j] = Wv[i * EE + j];
    __syncthreads();
    float acc = 0.0f;
    #pragma unroll 16
    for (int k = 0; k < EE; k++)
        acc = fmaf(wvrow[k], Wp[k * EE + j], acc);
    g_Wc[i * EE + j] = acc;
    if (i == 0) {
        float b = 0.0f;
        #pragma unroll 16
        for (int k = 0; k < EE; k++)
            b = fmaf(bv[k], Wp[k * EE + j], b);
        g_bc[j] = b;
    }
}

// ---------------------------------------------------------------------------
// Fill attn region with bp broadcast: 4 float4 stores per thread
__global__ void fill_bp_kernel(float4* __restrict__ out, const float4* __restrict__ bp4) {
    unsigned base = (blockIdx.x * blockDim.x + threadIdx.x) * 4;
    float4 v0 = bp4[(base + 0) & 31];
    float4 v1 = bp4[(base + 1) & 31];
    float4 v2 = bp4[(base + 2) & 31];
    float4 v3 = bp4[(base + 3) & 31];
    out[base + 0] = v0;
    out[base + 1] = v1;
    out[base + 2] = v2;
    out[base + 3] = v3;
}

// ---------------------------------------------------------------------------
// Fused output + adjacency ones: one block per TWO edges (2048 x 128).
// For each sub-edge: write A1/A2 ones (idempotent), and if first-src edge,
// gather same-src dsts, dedupe by value, sum value rows, matvec vs Wc.
__global__ __launch_bounds__(128)
void fused_out_kernel(float* __restrict__ attn,
                      float* __restrict__ A1,
                      float* __restrict__ A2,
                      const float* __restrict__ values,
                      const float* __restrict__ bp,
                      const int* __restrict__ edges) {
    __shared__ int ssrc[NEDGE];
    __shared__ int sdst[NEDGE];
    __shared__ int list[2][MAXL];
    __shared__ int nlist[2];
    __shared__ int dupflag[2];
    __shared__ float accv[2][EE];

    int b = blockIdx.y;
    int i0 = blockIdx.x * 2;              // edges i0, i0+1
    int e = threadIdx.x;

    const int4* eg = (const int4*)(edges + (size_t)b * NEDGE * 4);
    #pragma unroll
    for (int q = 0; q < 4; q++) {
        int t = e + q * EE;
        int4 v = eg[t];
        ssrc[t] = v.y * WIDTH + v.x;
        sdst[t] = v.w * WIDTH + v.z;
    }
    if (e < 2) { nlist[e] = 0; dupflag[e] = 0; }
    __syncthreads();

    // adjacency ones for both edges (after memset in stream order; idempotent)
    if (e < 2) {
        int i = i0 + e;
        size_t off = ((size_t)b * SS + ssrc[i]) * SS + sdst[i];
        A1[off] = 1.0f;
        A2[off] = 1.0f;
    }

    int my0 = ssrc[i0];
    int my1 = ssrc[i0 + 1];

    // 4 smem compares/thread per sub-edge: first-src check + dst collection
    #pragma unroll
    for (int q = 0; q < 4; q++) {
        int t = e + q * EE;
        int s = ssrc[t];
        if (s == my0) {
            if (t < i0) dupflag[0] = 1;
            int p = atomicAdd(&nlist[0], 1);
            if (p < MAXL) list[0][p] = sdst[t];
        }
        if (s == my1) {
            if (t < i0 + 1) dupflag[1] = 1;
            int p = atomicAdd(&nlist[1], 1);
            if (p < MAXL) list[1][p] = sdst[t];
        }
    }
    __syncthreads();
    int d0 = dupflag[0], d1 = dupflag[1];
    if (d0 && d1) return;

    // unique-by-value sums (order-independent => deterministic)
    int m0 = 0, m1 = 0;
    {
        float acc = 0.0f;
        if (!d0) {
            int n = nlist[0] < MAXL ? nlist[0] : MAXL;
            for (int q = 0; q < n; q++) {
                int d = list[0][q];
                bool uniq = true;
                for (int p = 0; p < q; p++)
                    if (list[0][p] == d) { uniq = false; break; }
                if (uniq) {
                    acc += values[((size_t)b * SS + d) * EE + e];
                    m0++;
                }
            }
        }
        accv[0][e] = acc;
    }
    {
        float acc = 0.0f;
        if (!d1) {
            int n = nlist[1] < MAXL ? nlist[1] : MAXL;
            for (int q = 0; q < n; q++) {
                int d = list[1][q];
                bool uniq = true;
                for (int p = 0; p < q; p++)
                    if (list[1][p] == d) { uniq = false; break; }
                if (uniq) {
                    acc += values[((size_t)b * SS + d) * EE + e];
                    m1++;
                }
            }
        }
        accv[1][e] = acc;
    }
    __syncthreads();

    // shared-weight matvec: each Wc element feeds both rows
    float bce = g_bc[e], bpe = bp[e];
    float o0 = fmaf((float)m0, bce, bpe);
    float o1 = fmaf((float)m1, bce, bpe);
    #pragma unroll 16
    for (int k = 0; k < EE; k++) {
        float w = g_Wc[k * EE + e];
        o0 = fmaf(accv[0][k], w, o0);
        o1 = fmaf(accv[1][k], w, o1);
    }

    if (!d0) attn[((size_t)b * SS + my0) * EE + e] = o0;
    if (!d1) attn[((size_t)b * SS + my1) * EE + e] = o1;
}

// ---------------------------------------------------------------------------
extern "C" void kernel_launch(void* const* d_in, const int* in_sizes, int n_in,
                              void* d_out, int out_size) {
    (void)in_sizes; (void)n_in; (void)out_size;

    const float* values = (const float*)d_in[2];
    const int*   edges  = (const int*)  d_in[3];
    const float* Wv     = (const float*)d_in[8];
    const float* bv     = (const float*)d_in[9];
    const float* Wp     = (const float*)d_in[10];
    const float* bp     = (const float*)d_in[11];

    float* out  = (float*)d_out;
    float* attn = out;                                    // [B,S,E]
    float* A1   = out + (size_t)BB * SS * EE;             // [B,S,S]
    float* A2   = A1 + (size_t)BB * SS * SS;              // [B,S,S]

    // 1) bulk zeros via memset (fastest store path, ~147 us)
    cudaMemsetAsync(A1, 0, 2ull * BB * SS * SS * sizeof(float));

    // 2) combined weights Wc, bc (~2.5 us)
    combine_kernel<<<EE, EE>>>(Wv, Wp, bv);

    // 3) attn := bp broadcast (~3-5 us)
    {
        unsigned total4 = BB * SS * (EE / 4);             // 1,048,576 float4s
        fill_bp_kernel<<<total4 / (256 * 4), 256>>>((float4*)attn, (const float4*)bp);
    }

    // 4) fused sparse output + adjacency ones (~11 us, 2048 blocks)
    {
        dim3 grid(NEDGE / 2, BB);
        fused_out_kernel<<<grid, EE>>>(attn, A1, A2, values, bp, edges);
    }
}

// round 14
// speedup vs baseline: 1.2502x; 1.0621x over previous
#include <cuda_runtime.h>
#include <cuda_bf16.h>
#include <cstdint>

#define BB 8
#define SS 4096           // WIDTH*WIDTH
#define EE 128
#define WIDTH 64
#define NEDGE 512         // 32 paths * 16 edges per batch
#define MAXL 32           // cap on same-src edge list
#define FILL_BLOCKS 2048  // 16 MB attn fill: 2048 blocks x 512 thr x 16 B

// Combined weights: Wc = Wv @ Wp, bc = bv @ Wp
__device__ float g_Wc[EE * EE];
__device__ float g_bc[EE];

// ---------------------------------------------------------------------------
// prep_fill: blocks [0,128)   -> Wc row i via split-K (4 chunks x 32 k-steps)
//            blocks [128, +FILL_BLOCKS) -> bp broadcast fill of attn region
__global__ __launch_bounds__(512)
void prep_fill_kernel(const float* __restrict__ Wv,
                      const float* __restrict__ Wp,
                      const float* __restrict__ bv,
                      float4* __restrict__ attn4,
                      const float4* __restrict__ bp4) {
    int t = threadIdx.x;
    if (blockIdx.x < EE) {
        // ---- combine: row i of Wc ----
        int i  = blockIdx.x;
        int j  = t & 127;
        int kc = t >> 7;                  // 0..3
        __shared__ float part[4][EE];
        __shared__ float wvrow[EE];
        if (kc == 0) wvrow[j] = Wv[i * EE + j];
        __syncthreads();

        float acc = 0.0f;
        int k0 = kc * 32;
        #pragma unroll
        for (int k = 0; k < 32; k++)
            acc = fmaf(wvrow[k0 + k], Wp[(k0 + k) * EE + j], acc);
        part[kc][j] = acc;
        __syncthreads();
        if (kc == 0) {
            g_Wc[i * EE + j] = (part[0][j] + part[1][j]) + (part[2][j] + part[3][j]);
        } else if (i == 0 && kc == 1) {
            // bc = bv @ Wp (independent 128-deep chain; only 1 warp-group, fine)
            float b = 0.0f;
            #pragma unroll 16
            for (int k = 0; k < EE; k++)
                b = fmaf(bv[k], Wp[k * EE + j], b);
            g_bc[j] = b;
        }
    } else {
        // ---- bp broadcast fill: 512 float4s per block ----
        unsigned idx = (blockIdx.x - EE) * 512u + t;
        attn4[idx] = bp4[t & 31];
    }
}

// ---------------------------------------------------------------------------
// Fused output + adjacency ones: one block per TWO edges (2048 x 128).
__global__ __launch_bounds__(128)
void fused_out_kernel(float* __restrict__ attn,
                      float* __restrict__ A1,
                      float* __restrict__ A2,
                      const float* __restrict__ values,
                      const float* __restrict__ bp,
                      const int* __restrict__ edges) {
    __shared__ int ssrc[NEDGE];
    __shared__ int sdst[NEDGE];
    __shared__ int list[2][MAXL];
    __shared__ int nlist[2];
    __shared__ int dupflag[2];
    __shared__ float accv[2][EE];

    int b = blockIdx.y;
    int i0 = blockIdx.x * 2;              // edges i0, i0+1
    int e = threadIdx.x;

    const int4* eg = (const int4*)(edges + (size_t)b * NEDGE * 4);
    #pragma unroll
    for (int q = 0; q < 4; q++) {
        int t = e + q * EE;
        int4 v = eg[t];
        ssrc[t] = v.y * WIDTH + v.x;
        sdst[t] = v.w * WIDTH + v.z;
    }
    if (e < 2) { nlist[e] = 0; dupflag[e] = 0; }
    __syncthreads();

    // adjacency ones for both edges (after memset in stream order; idempotent)
    if (e < 2) {
        int i = i0 + e;
        size_t off = ((size_t)b * SS + ssrc[i]) * SS + sdst[i];
        A1[off] = 1.0f;
        A2[off] = 1.0f;
    }

    int my0 = ssrc[i0];
    int my1 = ssrc[i0 + 1];

    // 4 smem compares/thread per sub-edge: first-src check + dst collection
    #pragma unroll
    for (int q = 0; q < 4; q++) {
        int t = e + q * EE;
        int s = ssrc[t];
        if (s == my0) {
            if (t < i0) dupflag[0] = 1;
            int p = atomicAdd(&nlist[0], 1);
            if (p < MAXL) list[0][p] = sdst[t];
        }
        if (s == my1) {
            if (t < i0 + 1) dupflag[1] = 1;
            int p = atomicAdd(&nlist[1], 1);
            if (p < MAXL) list[1][p] = sdst[t];
        }
    }
    __syncthreads();
    int d0 = dupflag[0], d1 = dupflag[1];
    if (d0 && d1) return;

    // unique-by-value sums (order-independent => deterministic)
    int m0 = 0, m1 = 0;
    {
        float acc = 0.0f;
        if (!d0) {
            int n = nlist[0] < MAXL ? nlist[0] : MAXL;
            for (int q = 0; q < n; q++) {
                int d = list[0][q];
                bool uniq = true;
                for (int p = 0; p < q; p++)
                    if (list[0][p] == d) { uniq = false; break; }
                if (uniq) {
                    acc += values[((size_t)b * SS + d) * EE + e];
                    m0++;
                }
            }
        }
        accv[0][e] = acc;
    }
    {
        float acc = 0.0f;
        if (!d1) {
            int n = nlist[1] < MAXL ? nlist[1] : MAXL;
            for (int q = 0; q < n; q++) {
                int d = list[1][q];
                bool uniq = true;
                for (int p = 0; p < q; p++)
                    if (list[1][p] == d) { uniq = false; break; }
                if (uniq) {
                    acc += values[((size_t)b * SS + d) * EE + e];
                    m1++;
                }
            }
        }
        accv[1][e] = acc;
    }
    __syncthreads();

    // shared-weight matvec: each Wc element feeds both rows
    float bce = g_bc[e], bpe = bp[e];
    float o0 = fmaf((float)m0, bce, bpe);
    float o1 = fmaf((float)m1, bce, bpe);
    #pragma unroll 16
    for (int k = 0; k < EE; k++) {
        float w = g_Wc[k * EE + e];
        o0 = fmaf(accv[0][k], w, o0);
        o1 = fmaf(accv[1][k], w, o1);
    }

    if (!d0) attn[((size_t)b * SS + my0) * EE + e] = o0;
    if (!d1) attn[((size_t)b * SS + my1) * EE + e] = o1;
}

// ---------------------------------------------------------------------------
extern "C" void kernel_launch(void* const* d_in, const int* in_sizes, int n_in,
                              void* d_out, int out_size) {
    (void)in_sizes; (void)n_in; (void)out_size;

    const float* values = (const float*)d_in[2];
    const int*   edges  = (const int*)  d_in[3];
    const float* Wv     = (const float*)d_in[8];
    const float* bv     = (const float*)d_in[9];
    const float* Wp     = (const float*)d_in[10];
    const float* bp     = (const float*)d_in[11];

    float* out  = (float*)d_out;
    float* attn = out;                                    // [B,S,E]
    float* A1   = out + (size_t)BB * SS * EE;             // [B,S,S]
    float* A2   = A1 + (size_t)BB * SS * SS;              // [B,S,S]

    // 1) bulk zeros via memset (fastest store path, ~147 us)
    cudaMemsetAsync(A1, 0, 2ull * BB * SS * SS * sizeof(float));

    // 2) combined weights + bp broadcast fill, one launch (~4-5 us)
    prep_fill_kernel<<<EE + FILL_BLOCKS, 512>>>(Wv, Wp, bv,
                                                (float4*)attn, (const float4*)bp);

    // 3) fused sparse output + adjacency ones (~10 us, 2048 blocks)
    {
        dim3 grid(NEDGE / 2, BB);
        fused_out_kernel<<<grid, EE>>>(attn, A1, A2, values, bp, edges);
    }
}